// round 5
// baseline (speedup 1.0000x reference)
#include <cuda_runtime.h>
#include <math.h>

#define DIM   1536
#define S_TOK 1560
#define NH    12
#define HD    128
#define CUR   9360
#define L_TOT 10920
#define LPAD  (L_TOT + 64)
#define W_GRID 52
#define SCALE 0.08838834764831845f

// Scratch
__device__ float g_q[S_TOK * DIM];      // raw Q proj
__device__ float g_k[S_TOK * DIM];      // raw K proj
__device__ float g_qp[S_TOK * DIM];     // normed+rope+hd-permuted Q (tf32)
__device__ float g_o[S_TOK * DIM];
__device__ float g_vtmp[S_TOK * DIM];   // rounded V proj (plain layout)
__device__ float g_ck[L_TOT * DIM];     // K window, hd-permuted, tf32
__device__ float g_cvT[NH * 128 * LPAD];// V window, [head][hd][permtok], tf32

__device__ __forceinline__ unsigned int f2tf(float f) {
    unsigned int u;
    asm("cvt.rna.tf32.f32 %0, %1;" : "=r"(u) : "f"(f));
    return u;
}
__device__ __forceinline__ float f2tff(float f) { return __uint_as_float(f2tf(f)); }

__device__ __forceinline__ int permhd(int d) {   // pair-perm within 8-groups
    int a = d & ~7, r = d & 7;
    return a + ((r < 4) ? 2 * r : 2 * (r - 4) + 1);
}

__device__ __forceinline__ void mma_tf32(float c[4], unsigned int a0, unsigned int a1,
                                         unsigned int a2, unsigned int a3,
                                         unsigned int b0, unsigned int b1) {
    asm("mma.sync.aligned.m16n8k8.row.col.f32.tf32.tf32.f32 "
        "{%0,%1,%2,%3}, {%4,%5,%6,%7}, {%8,%9}, {%0,%1,%2,%3};"
        : "+f"(c[0]), "+f"(c[1]), "+f"(c[2]), "+f"(c[3])
        : "r"(a0), "r"(a1), "r"(a2), "r"(a3), "r"(b0), "r"(b1));
}

__device__ __forceinline__ void cp16(unsigned int s_addr, const void* gptr) {
    asm volatile("cp.async.ca.shared.global [%0], [%1], 16;\n" :: "r"(s_addr), "l"(gptr));
}
__device__ __forceinline__ void cp_commit() { asm volatile("cp.async.commit_group;\n"); }
template <int N> __device__ __forceinline__ void cp_wait() {
    asm volatile("cp.async.wait_group %0;\n" :: "n"(N));
}

// ---------------------------------------------------------------------------
// preround K cache -> g_ck (hd-permuted, tf32-rounded)
// ---------------------------------------------------------------------------
__global__ __launch_bounds__(256)
void preround_k_kernel(const float* __restrict__ ck) {
    const size_t n = (size_t)CUR * DIM;
    for (size_t i = (size_t)blockIdx.x * 1024 + threadIdx.x * 4; i < n;
         i += (size_t)gridDim.x * 1024) {
        float4 v = *(const float4*)(ck + i);
        int rem = (int)(i % DIM);
        int base = (int)(i - rem);
        int h = rem >> 7, d = rem & 127;
        float* dst = g_ck + base + h * 128;
        dst[permhd(d)]     = f2tff(v.x);
        dst[permhd(d + 1)] = f2tff(v.y);
        dst[permhd(d + 2)] = f2tff(v.z);
        dst[permhd(d + 3)] = f2tff(v.w);
    }
}

// ---------------------------------------------------------------------------
// V transpose: (cache_v rounded | g_vtmp) -> g_cvT[head][hd][permtok]
// block = 24 tokens x 128 hd for one head
// ---------------------------------------------------------------------------
__global__ __launch_bounds__(256)
void transpose_v_kernel(const float* __restrict__ cv) {
    __shared__ float ts[24][132];
    const int head = blockIdx.y;
    const int tb = blockIdx.x * 24;
    const int tid = threadIdx.x;
#pragma unroll
    for (int i = 0; i < 12; i++) {
        int idx = tid + i * 256;
        int t = idx >> 7, d = idx & 127;
        int tg = tb + t;
        float v = (tg < CUR) ? f2tff(cv[(size_t)tg * DIM + head * 128 + d])
                             : g_vtmp[(size_t)(tg - CUR) * DIM + head * 128 + d];
        ts[t][d] = v;
    }
    __syncthreads();
    float* out = g_cvT + (size_t)head * 128 * LPAD;
#pragma unroll
    for (int i = 0; i < 12; i++) {
        int j = tid + i * 256;
        int d = j / 24, p = j % 24;
        int pp = (p & ~7) + (((p & 7) < 4) ? 2 * (p & 7) : 2 * ((p & 7) - 4) + 1);
        out[(size_t)d * LPAD + tb + pp] = ts[p][d];
    }
}

// ---------------------------------------------------------------------------
// tf32 GEMM: C = A @ B^T + bias (128x128, BK=32, 8 warps)
// ---------------------------------------------------------------------------
#define GSTR 36

__device__ __forceinline__ void gemm_body(const float* __restrict__ A,
                                          const float* __restrict__ B,
                                          const float* __restrict__ bias,
                                          float* __restrict__ C, int M, int rnd) {
    __shared__ unsigned int As[128 * GSTR];
    __shared__ unsigned int Bs[128 * GSTR];
    const int tid = threadIdx.x;
    const int m0 = blockIdx.y * 128;
    const int n0 = blockIdx.x * 128;
    const int lane = tid & 31;
    const int w = tid >> 5;
    const int g = lane >> 2;
    const int tg = lane & 3;
    const int wy = w >> 1;
    const int wx = w & 1;
    const int r = tid >> 1;
    const int cbase = (tid & 1) * 16;

    float acc[2][8][4];
#pragma unroll
    for (int mf = 0; mf < 2; mf++)
#pragma unroll
        for (int nf = 0; nf < 8; nf++)
#pragma unroll
            for (int j = 0; j < 4; j++) acc[mf][nf][j] = 0.f;

    const bool avalid = (m0 + r) < M;
    const float* pa = A + (size_t)(m0 + r) * DIM + cbase;
    const float* pb = B + (size_t)(n0 + r) * DIM + cbase;

    for (int k0 = 0; k0 < DIM; k0 += 32) {
#pragma unroll
        for (int i = 0; i < 4; i++) {
            float4 v = avalid ? *(const float4*)(pa + k0 + i * 4)
                              : make_float4(0.f, 0.f, 0.f, 0.f);
            *(uint4*)&As[r * GSTR + cbase + i * 4] =
                make_uint4(f2tf(v.x), f2tf(v.y), f2tf(v.z), f2tf(v.w));
        }
#pragma unroll
        for (int i = 0; i < 4; i++) {
            float4 v = *(const float4*)(pb + k0 + i * 4);
            *(uint4*)&Bs[r * GSTR + cbase + i * 4] =
                make_uint4(f2tf(v.x), f2tf(v.y), f2tf(v.z), f2tf(v.w));
        }
        __syncthreads();
#pragma unroll
        for (int kc = 0; kc < 32; kc += 8) {
            unsigned int a[2][4];
#pragma unroll
            for (int mf = 0; mf < 2; mf++) {
                const int row = wy * 32 + mf * 16 + g;
                a[mf][0] = As[row * GSTR + kc + tg];
                a[mf][1] = As[(row + 8) * GSTR + kc + tg];
                a[mf][2] = As[row * GSTR + kc + tg + 4];
                a[mf][3] = As[(row + 8) * GSTR + kc + tg + 4];
            }
#pragma unroll
            for (int nf = 0; nf < 8; nf++) {
                const int brow = wx * 64 + nf * 8 + g;
                unsigned int b0 = Bs[brow * GSTR + kc + tg];
                unsigned int b1 = Bs[brow * GSTR + kc + tg + 4];
                mma_tf32(acc[0][nf], a[0][0], a[0][1], a[0][2], a[0][3], b0, b1);
                mma_tf32(acc[1][nf], a[1][0], a[1][1], a[1][2], a[1][3], b0, b1);
            }
        }
        __syncthreads();
    }

#pragma unroll
    for (int mf = 0; mf < 2; mf++) {
        const int row = m0 + wy * 32 + mf * 16 + g;
#pragma unroll
        for (int nf = 0; nf < 8; nf++) {
            const int col = n0 + wx * 64 + nf * 8 + 2 * tg;
            const float b0 = bias[col], b1 = bias[col + 1];
            float v00 = acc[mf][nf][0] + b0, v01 = acc[mf][nf][1] + b1;
            float v10 = acc[mf][nf][2] + b0, v11 = acc[mf][nf][3] + b1;
            if (rnd) { v00 = f2tff(v00); v01 = f2tff(v01); v10 = f2tff(v10); v11 = f2tff(v11); }
            if (row < M)
                *(float2*)(C + (size_t)row * DIM + col) = make_float2(v00, v01);
            if (row + 8 < M)
                *(float2*)(C + (size_t)(row + 8) * DIM + col) = make_float2(v10, v11);
        }
    }
}

__global__ __launch_bounds__(256, 2)
void gemm_qkv_kernel(const float* __restrict__ A,
                     const float* __restrict__ wq, const float* __restrict__ bq,
                     const float* __restrict__ wk, const float* __restrict__ bk,
                     const float* __restrict__ wv, const float* __restrict__ bv,
                     int M) {
    const float *B, *bias; float* C; int rnd;
    if (blockIdx.z == 0)      { B = wq; bias = bq; C = g_q;    rnd = 0; }
    else if (blockIdx.z == 1) { B = wk; bias = bk; C = g_k;    rnd = 0; }
    else                      { B = wv; bias = bv; C = g_vtmp; rnd = 1; }
    gemm_body(A, B, bias, C, M, rnd);
}

__global__ __launch_bounds__(256, 2)
void gemm_out_kernel(const float* __restrict__ A, const float* __restrict__ B,
                     const float* __restrict__ bias, float* __restrict__ C, int M) {
    gemm_body(A, B, bias, C, M, 0);
}

// ---------------------------------------------------------------------------
// rmsnorm + RoPE; output tf32-rounded, hd-permuted, to dst (!= src)
// ---------------------------------------------------------------------------
__global__ __launch_bounds__(256)
void norm_rope_kernel(const float* __restrict__ src, float* __restrict__ dst,
                      const float* __restrict__ g,
                      const float* __restrict__ fcos, const float* __restrict__ fsin) {
    const int s = blockIdx.x;
    const float* row = src + (size_t)s * DIM;
    float* orow = dst + (size_t)s * DIM;
    __shared__ float red[256];

    float ss = 0.f;
    for (int i = threadIdx.x; i < DIM; i += 256) {
        float v = row[i];
        ss += v * v;
    }
    red[threadIdx.x] = ss;
    __syncthreads();
    for (int off = 128; off > 0; off >>= 1) {
        if (threadIdx.x < off) red[threadIdx.x] += red[threadIdx.x + off];
        __syncthreads();
    }
    const float scale = rsqrtf(red[0] * (1.0f / DIM) + 1e-6f);

    const int hh = s / W_GRID;
    const int ww = s % W_GRID;
    for (int p = threadIdx.x; p < NH * 64; p += 256) {
        const int head = p >> 6;
        const int c = p & 63;
        const int trow = (c < 22) ? 6 : ((c < 43) ? hh : ww);
        const float cv = fcos[trow * 64 + c];
        const float sv = fsin[trow * 64 + c];
        const int base = head * HD + 2 * c;
        const float xr = row[base] * scale * g[base];
        const float xi = row[base + 1] * scale * g[base + 1];
        orow[head * HD + permhd(2 * c)]     = f2tff(xr * cv - xi * sv);
        orow[head * HD + permhd(2 * c + 1)] = f2tff(xr * sv + xi * cv);
    }
}

// ---------------------------------------------------------------------------
// tf32 flash attention. BQ=160 x BK=64, 10 warps (320 thr), grid 10x12=120.
// Score: warp = 32q x 32k (mf=2). PV: warp = 32q x 64hd (mf=2).
// All fragment loads are LDS.64 via pairing layouts; strides == 8 mod 32.
// ---------------------------------------------------------------------------
#define BQ 160
#define BK 64
#define QSTR 136
#define KSTR 136
#define VSTR 72
#define PSTR 72
#define NTHR 320

struct AttnSmem {
    unsigned int Qs[BQ * QSTR];
    unsigned int Ks[BK * KSTR];
    unsigned int Vs[128 * VSTR];   // [hd][permtok]
    float Ps[BQ * PSTR];
    float row_m[BQ];
    float row_l[BQ];
    float row_a[BQ];
};
#define ATTN_SMEM ((int)sizeof(AttnSmem))

__global__ __launch_bounds__(NTHR, 1)
void attn_tc_kernel(const float* __restrict__ q, float* __restrict__ out) {
    extern __shared__ char smraw[];
    AttnSmem* sm = (AttnSmem*)smraw;

    const int head = blockIdx.y;
    const int q0 = blockIdx.x * BQ;
    const int tid = threadIdx.x;
    const int lane = tid & 31;
    const int w = tid >> 5;          // 0..9
    const int g = lane >> 2;
    const int tg = lane & 3;
    const int wy = w >> 1;           // 0..4 -> q-base *32
    const int wx = w & 1;            // score: k half; PV: hd half

    const unsigned int smem_base = (unsigned int)__cvta_generic_to_shared(sm);
    const unsigned int ks_base = smem_base + (unsigned int)((char*)sm->Ks - (char*)sm);
    const unsigned int vs_base = smem_base + (unsigned int)((char*)sm->Vs - (char*)sm);

    const bool loader = tid < 256;
    const int klr = tid >> 2;           // 0..63
    const int klc = (tid & 3) * 32;
    const int vlr = tid >> 1;           // 0..127
    const int vlc = (tid & 1) * 32;

    const float* cvT_head = g_cvT + (size_t)head * 128 * LPAD;

    // ---- load Q tile ----
    {
        const int r = tid >> 1;          // 0..159
        const int cbase = (tid & 1) * 64;
        const int srow = q0 + r;
        const bool valid = srow < S_TOK;
        const float* src = q + (size_t)srow * DIM + head * HD;
#pragma unroll
        for (int m2 = 0; m2 < 16; m2++) {
            int d = cbase + m2 * 4;
            float4 v = valid ? *(const float4*)(src + d) : make_float4(0.f, 0.f, 0.f, 0.f);
            *(float4*)&sm->Qs[r * QSTR + d] = v;
        }
    }
    if (tid < BQ) { sm->row_m[tid] = -1e30f; sm->row_l[tid] = 0.f; }

    float acc[2][8][4];
#pragma unroll
    for (int mf = 0; mf < 2; mf++)
#pragma unroll
        for (int nf = 0; nf < 8; nf++)
#pragma unroll
            for (int j = 0; j < 4; j++) acc[mf][nf][j] = 0.f;

    const int NT = (L_TOT + BK - 1) / BK;  // 171

    // prologue: K(0)
    if (loader) {
        const int kidx = min(klr, L_TOT - 1);
        const float* src = g_ck + (size_t)kidx * DIM + head * HD + klc;
#pragma unroll
        for (int i = 0; i < 8; i++)
            cp16(ks_base + (klr * KSTR + klc + i * 4) * 4, src + i * 4);
    }
    cp_commit();
    __syncthreads();

    // score->Ps permuted column positions for this thread
    const int pcol0 = (tg < 2) ? 4 * tg : 4 * tg - 7;
    const int pcol1 = (tg < 2) ? 4 * tg + 2 : 4 * tg - 5;
    // softmax rotation (conflict-free banks)
    const int rot = (lane - 8 * ((lane >> 1) & 3)) & 31;

    for (int t = 0; t < NT; t++) {
        const int kbase = t * BK;

        // issue V(t): Vs[hd][tok] from transposed global (already permuted)
        if (loader) {
            const float* src = cvT_head + (size_t)vlr * LPAD + kbase + vlc;
#pragma unroll
            for (int i = 0; i < 8; i++)
                cp16(vs_base + (vlr * VSTR + vlc + i * 4) * 4, src + i * 4);
        }
        cp_commit();

        cp_wait<1>();      // K(t) ready
        __syncthreads();

        // ---- scores: warp = 32q x 32k ----
        {
            float sc[2][4][4];
#pragma unroll
            for (int mf = 0; mf < 2; mf++)
#pragma unroll
                for (int nf = 0; nf < 4; nf++)
#pragma unroll
                    for (int j = 0; j < 4; j++) sc[mf][nf][j] = 0.f;

#pragma unroll 4
            for (int kf = 0; kf < 16; kf++) {
                const int kc = kf * 8 + 2 * tg;
                unsigned int a[2][4];
#pragma unroll
                for (int mf = 0; mf < 2; mf++) {
                    const int row = wy * 32 + mf * 16 + g;
                    uint2 lo = *(const uint2*)&sm->Qs[row * QSTR + kc];
                    uint2 hi = *(const uint2*)&sm->Qs[(row + 8) * QSTR + kc];
                    a[mf][0] = lo.x; a[mf][1] = hi.x; a[mf][2] = lo.y; a[mf][3] = hi.y;
                }
#pragma unroll
                for (int nf = 0; nf < 4; nf++) {
                    const int brow = wx * 32 + nf * 8 + g;
                    uint2 b = *(const uint2*)&sm->Ks[brow * KSTR + kc];
                    mma_tf32(sc[0][nf], a[0][0], a[0][1], a[0][2], a[0][3], b.x, b.y);
                    mma_tf32(sc[1][nf], a[1][0], a[1][1], a[1][2], a[1][3], b.x, b.y);
                }
            }
            // write scores at k-permuted columns
#pragma unroll
            for (int mf = 0; mf < 2; mf++) {
                const int row = wy * 32 + mf * 16 + g;
#pragma unroll
                for (int nf = 0; nf < 4; nf++) {
                    const int cb = wx * 32 + nf * 8;
                    const int k0i = kbase + cb + 2 * tg;
                    const bool v0 = k0i < L_TOT;
                    const bool v1 = k0i + 1 < L_TOT;
                    sm->Ps[row * PSTR + cb + pcol0]       = v0 ? sc[mf][nf][0] * SCALE : -1e30f;
                    sm->Ps[row * PSTR + cb + pcol1]       = v1 ? sc[mf][nf][1] * SCALE : -1e30f;
                    sm->Ps[(row + 8) * PSTR + cb + pcol0] = v0 ? sc[mf][nf][2] * SCALE : -1e30f;
                    sm->Ps[(row + 8) * PSTR + cb + pcol1] = v1 ? sc[mf][nf][3] * SCALE : -1e30f;
                }
            }
        }
        __syncthreads();   // Ps done; Ks free

        // issue K(t+1)
        if (loader) {
            const int kidx = min(min(t + 1, NT - 1) * BK + klr, L_TOT - 1);
            const float* src = g_ck + (size_t)kidx * DIM + head * HD + klc;
#pragma unroll
            for (int i = 0; i < 8; i++)
                cp16(ks_base + (klr * KSTR + klc + i * 4) * 4, src + i * 4);
        }
        cp_commit();

        // ---- softmax (2 threads/row, rotated columns) ----
        {
            const int r = tid >> 1;        // 0..159
            const int part = (tid & 1) * 32;
            float mx = -1e30f;
#pragma unroll
            for (int jj = 0; jj < 32; jj++) {
                const int c = part + ((jj + rot) & 31);
                mx = fmaxf(mx, sm->Ps[r * PSTR + c]);
            }
            mx = fmaxf(mx, __shfl_xor_sync(0xffffffffu, mx, 1));
            const float m_old = sm->row_m[r];
            const float m_new = fmaxf(m_old, mx);
            float sum = 0.f;
            unsigned int* Pu = (unsigned int*)sm->Ps;
#pragma unroll
            for (int jj = 0; jj < 32; jj++) {
                const int c = part + ((jj + rot) & 31);
                float p = __expf(sm->Ps[r * PSTR + c] - m_new);
                Pu[r * PSTR + c] = f2tf(p);
                sum += p;
            }
            sum += __shfl_xor_sync(0xffffffffu, sum, 1);
            if ((tid & 1) == 0) {
                const float al = __expf(m_old - m_new);
                sm->row_a[r] = al;
                sm->row_l[r] = sm->row_l[r] * al + sum;
                sm->row_m[r] = m_new;
            }
        }

        cp_wait<1>();      // V(t) ready
        __syncthreads();

        // ---- PV: warp = 32q x 64hd ----
        {
#pragma unroll
            for (int mf = 0; mf < 2; mf++) {
                const int row = wy * 32 + mf * 16 + g;
                const float aA = sm->row_a[row];
                const float aB = sm->row_a[row + 8];
#pragma unroll
                for (int nf = 0; nf < 8; nf++) {
                    acc[mf][nf][0] *= aA; acc[mf][nf][1] *= aA;
                    acc[mf][nf][2] *= aB; acc[mf][nf][3] *= aB;
                }
            }
            const unsigned int* Pu = (const unsigned int*)sm->Ps;
#pragma unroll 2
            for (int kf = 0; kf < 8; kf++) {
                const int kc = kf * 8 + 2 * tg;
                unsigned int a[2][4];
#pragma unroll
                for (int mf = 0; mf < 2; mf++) {
                    const int row = wy * 32 + mf * 16 + g;
                    uint2 lo = *(const uint2*)&Pu[row * PSTR + kc];
                    uint2 hi = *(const uint2*)&Pu[(row + 8) * PSTR + kc];
                    a[mf][0] = lo.x; a[mf][1] = hi.x; a[mf][2] = lo.y; a[mf][3] = hi.y;
                }
#pragma unroll
                for (int nf = 0; nf < 8; nf++) {
                    const int col = wx * 64 + nf * 8 + g;   // hd index
                    uint2 b = *(const uint2*)&sm->Vs[col * VSTR + kc];
                    mma_tf32(acc[0][nf], a[0][0], a[0][1], a[0][2], a[0][3], b.x, b.y);
                    mma_tf32(acc[1][nf], a[1][0], a[1][1], a[1][2], a[1][3], b.x, b.y);
                }
            }
        }
        __syncthreads();
    }

    // ---- epilogue ----
#pragma unroll
    for (int mf = 0; mf < 2; mf++) {
        const int rbase = wy * 32 + mf * 16 + g;
        const float inv  = 1.0f / sm->row_l[rbase];
        const float inv8 = 1.0f / sm->row_l[rbase + 8];
        const int row  = q0 + rbase;
        const int row8 = row + 8;
#pragma unroll
        for (int nf = 0; nf < 8; nf++) {
            const int col = head * HD + wx * 64 + nf * 8 + 2 * tg;
            if (row < S_TOK)
                *(float2*)(out + (size_t)row * DIM + col) =
                    make_float2(acc[mf][nf][0] * inv, acc[mf][nf][1] * inv);
            if (row8 < S_TOK)
                *(float2*)(out + (size_t)row8 * DIM + col) =
                    make_float2(acc[mf][nf][2] * inv8, acc[mf][nf][3] * inv8);
        }
    }
}

// ---------------------------------------------------------------------------
extern "C" void kernel_launch(void* const* d_in, const int* in_sizes, int n_in,
                              void* d_out, int out_size) {
    (void)in_sizes; (void)n_in; (void)out_size;
    const float* x    = (const float*)d_in[0];
    const float* wq   = (const float*)d_in[1];
    const float* bq   = (const float*)d_in[2];
    const float* wk   = (const float*)d_in[3];
    const float* bk   = (const float*)d_in[4];
    const float* wv   = (const float*)d_in[5];
    const float* bv   = (const float*)d_in[6];
    const float* wo   = (const float*)d_in[7];
    const float* bo   = (const float*)d_in[8];
    const float* gq   = (const float*)d_in[9];
    const float* gk   = (const float*)d_in[10];
    const float* fcos = (const float*)d_in[11];
    const float* fsin = (const float*)d_in[12];
    const float* ck   = (const float*)d_in[13];
    const float* cvv  = (const float*)d_in[14];

    float *q, *k, *qp, *o, *gck;
    cudaGetSymbolAddress((void**)&q, g_q);
    cudaGetSymbolAddress((void**)&k, g_k);
    cudaGetSymbolAddress((void**)&qp, g_qp);
    cudaGetSymbolAddress((void**)&o, g_o);
    cudaGetSymbolAddress((void**)&gck, g_ck);

    cudaFuncSetAttribute(attn_tc_kernel, cudaFuncAttributeMaxDynamicSharedMemorySize,
                         ATTN_SMEM);

    // 1. preround K cache (hd-permuted)
    preround_k_kernel<<<2048, 256>>>(ck);

    // 2. fused Q/K/V projections
    dim3 qkvgrid(DIM / 128, (S_TOK + 127) / 128, 3);
    gemm_qkv_kernel<<<qkvgrid, 256>>>(x, wq, bq, wk, bk, wv, bv, S_TOK);

    // 3. norm+rope (hd-permuted out): Q -> g_qp, K -> g_ck tail
    norm_rope_kernel<<<S_TOK, 256>>>(q, qp, gq, fcos, fsin);
    norm_rope_kernel<<<S_TOK, 256>>>(k, gck + (size_t)CUR * DIM, gk, fcos, fsin);

    // 4. V transpose into [head][hd][permtok]
    dim3 tvgrid(L_TOT / 24, NH);   // (455, 12)
    transpose_v_kernel<<<tvgrid, 256>>>(cvv);

    // 5. attention (120 blocks, one wave)
    dim3 agrid((S_TOK + BQ - 1) / BQ, NH);  // (10, 12)
    attn_tc_kernel<<<agrid, NTHR, ATTN_SMEM>>>(qp, o);

    // 6. output projection
    dim3 ogrid(DIM / 128, (S_TOK + 127) / 128);
    gemm_out_kernel<<<ogrid, 256>>>(o, wo, bo, (float*)d_out, S_TOK);
}

// round 6
// speedup vs baseline: 1.2175x; 1.2175x over previous
#include <cuda_runtime.h>
#include <math.h>

// Problem constants (fixed by setup_inputs)
#define DIM   1536
#define S_TOK 1560
#define NH    12
#define HD    128
#define CUR   9360          // current_start
#define L_TOT 10920         // KV window length (w0 = 0)
#define W_GRID 52
#define SCALE 0.08838834764831845f          // 1/sqrt(128)
#define SCALE_LOG2E 0.12751776466576712f    // SCALE * log2(e)

// Scratch (allocation-free: __device__ globals)
__device__ float g_q[S_TOK * DIM];
__device__ float g_k[S_TOK * DIM];
__device__ float g_o[S_TOK * DIM];
// Unified tf32-rounded KV window, layout [token][head][hd] (stride DIM)
__device__ float g_ck[L_TOT * DIM];
__device__ float g_cv[L_TOT * DIM];

__device__ __forceinline__ unsigned int f2tf(float f) {
    unsigned int u;
    asm("cvt.rna.tf32.f32 %0, %1;" : "=r"(u) : "f"(f));
    return u;
}
__device__ __forceinline__ float f2tff(float f) { return __uint_as_float(f2tf(f)); }

__device__ __forceinline__ void mma_tf32(float c[4], unsigned int a0, unsigned int a1,
                                         unsigned int a2, unsigned int a3,
                                         unsigned int b0, unsigned int b1) {
    asm("mma.sync.aligned.m16n8k8.row.col.f32.tf32.tf32.f32 "
        "{%0,%1,%2,%3}, {%4,%5,%6,%7}, {%8,%9}, {%0,%1,%2,%3};"
        : "+f"(c[0]), "+f"(c[1]), "+f"(c[2]), "+f"(c[3])
        : "r"(a0), "r"(a1), "r"(a2), "r"(a3), "r"(b0), "r"(b1));
}

__device__ __forceinline__ void cp16(unsigned int s_addr, const void* gptr) {
    asm volatile("cp.async.ca.shared.global [%0], [%1], 16;\n" :: "r"(s_addr), "l"(gptr));
}
__device__ __forceinline__ void cp_commit() { asm volatile("cp.async.commit_group;\n"); }
template <int N> __device__ __forceinline__ void cp_wait() {
    asm volatile("cp.async.wait_group %0;\n" :: "n"(N));
}

// ---------------------------------------------------------------------------
// Preround: cache K/V -> tf32-rounded scratch (first CUR tokens)
// ---------------------------------------------------------------------------
__global__ __launch_bounds__(256)
void preround_kernel(const float* __restrict__ ck, const float* __restrict__ cv) {
    const size_t n = (size_t)CUR * DIM;
    size_t i = ((size_t)blockIdx.x * 256 + threadIdx.x) * 4;
    const size_t stride = (size_t)gridDim.x * 256 * 4;
    for (; i < n; i += stride) {
        float4 a = *(const float4*)(ck + i);
        float4 b = *(const float4*)(cv + i);
        *(float4*)(g_ck + i) = make_float4(f2tff(a.x), f2tff(a.y), f2tff(a.z), f2tff(a.w));
        *(float4*)(g_cv + i) = make_float4(f2tff(b.x), f2tff(b.y), f2tff(b.z), f2tff(b.w));
    }
}

// ---------------------------------------------------------------------------
// tf32 GEMM: C = A @ B^T + bias. 128x128 tile, BK=32, 8 warps.
// ---------------------------------------------------------------------------
#define GSTR 36

__device__ __forceinline__ void gemm_body(const float* __restrict__ A,
                                          const float* __restrict__ B,
                                          const float* __restrict__ bias,
                                          float* __restrict__ C, int M, int rnd) {
    __shared__ unsigned int As[128 * GSTR];
    __shared__ unsigned int Bs[128 * GSTR];
    const int tid = threadIdx.x;
    const int m0 = blockIdx.y * 128;
    const int n0 = blockIdx.x * 128;
    const int lane = tid & 31;
    const int w = tid >> 5;
    const int g = lane >> 2;
    const int tg = lane & 3;
    const int wy = w >> 1;
    const int wx = w & 1;
    const int r = tid >> 1;
    const int cbase = (tid & 1) * 16;

    float acc[2][8][4];
#pragma unroll
    for (int mf = 0; mf < 2; mf++)
#pragma unroll
        for (int nf = 0; nf < 8; nf++)
#pragma unroll
            for (int j = 0; j < 4; j++) acc[mf][nf][j] = 0.f;

    const bool avalid = (m0 + r) < M;
    const float* pa = A + (size_t)(m0 + r) * DIM + cbase;
    const float* pb = B + (size_t)(n0 + r) * DIM + cbase;

    for (int k0 = 0; k0 < DIM; k0 += 32) {
#pragma unroll
        for (int i = 0; i < 4; i++) {
            float4 v = avalid ? *(const float4*)(pa + k0 + i * 4)
                              : make_float4(0.f, 0.f, 0.f, 0.f);
            *(uint4*)&As[r * GSTR + cbase + i * 4] =
                make_uint4(f2tf(v.x), f2tf(v.y), f2tf(v.z), f2tf(v.w));
        }
#pragma unroll
        for (int i = 0; i < 4; i++) {
            float4 v = *(const float4*)(pb + k0 + i * 4);
            *(uint4*)&Bs[r * GSTR + cbase + i * 4] =
                make_uint4(f2tf(v.x), f2tf(v.y), f2tf(v.z), f2tf(v.w));
        }
        __syncthreads();
#pragma unroll
        for (int kc = 0; kc < 32; kc += 8) {
            unsigned int a[2][4];
#pragma unroll
            for (int mf = 0; mf < 2; mf++) {
                const int row = wy * 32 + mf * 16 + g;
                a[mf][0] = As[row * GSTR + kc + tg];
                a[mf][1] = As[(row + 8) * GSTR + kc + tg];
                a[mf][2] = As[row * GSTR + kc + tg + 4];
                a[mf][3] = As[(row + 8) * GSTR + kc + tg + 4];
            }
#pragma unroll
            for (int nf = 0; nf < 8; nf++) {
                const int brow = wx * 64 + nf * 8 + g;
                unsigned int b0 = Bs[brow * GSTR + kc + tg];
                unsigned int b1 = Bs[brow * GSTR + kc + tg + 4];
                mma_tf32(acc[0][nf], a[0][0], a[0][1], a[0][2], a[0][3], b0, b1);
                mma_tf32(acc[1][nf], a[1][0], a[1][1], a[1][2], a[1][3], b0, b1);
            }
        }
        __syncthreads();
    }

#pragma unroll
    for (int mf = 0; mf < 2; mf++) {
        const int row = m0 + wy * 32 + mf * 16 + g;
#pragma unroll
        for (int nf = 0; nf < 8; nf++) {
            const int col = n0 + wx * 64 + nf * 8 + 2 * tg;
            const float b0 = bias[col], b1 = bias[col + 1];
            float v00 = acc[mf][nf][0] + b0, v01 = acc[mf][nf][1] + b1;
            float v10 = acc[mf][nf][2] + b0, v11 = acc[mf][nf][3] + b1;
            if (rnd) { v00 = f2tff(v00); v01 = f2tff(v01); v10 = f2tff(v10); v11 = f2tff(v11); }
            if (row < M)
                *(float2*)(C + (size_t)row * DIM + col) = make_float2(v00, v01);
            if (row + 8 < M)
                *(float2*)(C + (size_t)(row + 8) * DIM + col) = make_float2(v10, v11);
        }
    }
}

__global__ __launch_bounds__(256, 2)
void gemm_qkv_kernel(const float* __restrict__ A,
                     const float* __restrict__ wq, const float* __restrict__ bq,
                     const float* __restrict__ wk, const float* __restrict__ bk,
                     const float* __restrict__ wv, const float* __restrict__ bv,
                     int M) {
    const float *B, *bias; float* C; int rnd;
    if (blockIdx.z == 0)      { B = wq; bias = bq; C = g_q; rnd = 0; }
    else if (blockIdx.z == 1) { B = wk; bias = bk; C = g_k; rnd = 0; }
    else                      { B = wv; bias = bv; C = g_cv + (size_t)CUR * DIM; rnd = 1; }
    gemm_body(A, B, bias, C, M, rnd);
}

__global__ __launch_bounds__(256, 2)
void gemm_out_kernel(const float* __restrict__ A, const float* __restrict__ B,
                     const float* __restrict__ bias, float* __restrict__ C, int M) {
    gemm_body(A, B, bias, C, M, 0);
}

// ---------------------------------------------------------------------------
// rmsnorm + RoPE, output scaled by oscale and tf32-rounded
// ---------------------------------------------------------------------------
__global__ __launch_bounds__(256)
void norm_rope_kernel(const float* __restrict__ src, float* __restrict__ dst,
                      const float* __restrict__ g,
                      const float* __restrict__ fcos, const float* __restrict__ fsin,
                      float oscale) {
    const int s = blockIdx.x;
    const float* row = src + (size_t)s * DIM;
    float* orow = dst + (size_t)s * DIM;
    __shared__ float red[256];

    float ss = 0.f;
    for (int i = threadIdx.x; i < DIM; i += 256) {
        float v = row[i];
        ss += v * v;
    }
    red[threadIdx.x] = ss;
    __syncthreads();
    for (int off = 128; off > 0; off >>= 1) {
        if (threadIdx.x < off) red[threadIdx.x] += red[threadIdx.x + off];
        __syncthreads();
    }
    const float scale = rsqrtf(red[0] * (1.0f / DIM) + 1e-6f);

    const int hh = s / W_GRID;
    const int ww = s % W_GRID;
    for (int p = threadIdx.x; p < NH * 64; p += 256) {
        const int head = p >> 6;
        const int c = p & 63;
        const int trow = (c < 22) ? 6 : ((c < 43) ? hh : ww);
        const float cv = fcos[trow * 64 + c];
        const float sv = fsin[trow * 64 + c];
        const int base = head * HD + 2 * c;
        const float xr = row[base] * scale * g[base];
        const float xi = row[base + 1] * scale * g[base + 1];
        orow[base]     = f2tff((xr * cv - xi * sv) * oscale);
        orow[base + 1] = f2tff((xr * sv + xi * cv) * oscale);
    }
}

// ---------------------------------------------------------------------------
// tf32 flash attention. BQ=144 x BK=64, 9 warps (288 thr), grid 11x12=132.
// Warp w owns q-rows [16w, 16w+16) for score, softmax AND PV:
//  - softmax fully in registers (shfl over the 4 tg-lanes of each row)
//  - m/l/alpha in registers, P handed to PV via smem + __syncwarp only
//  - K double-buffered (no barrier between score and K(t+1) issue)
// Scores arrive pre-scaled to base-2 domain (SCALE*log2e folded into Q).
// ---------------------------------------------------------------------------
#define BQ 144
#define BK 64
#define QSTR 132
#define KSTR 132
#define VSTR 136
#define PSTR 68
#define NTHR 288

struct AttnSmem {
    unsigned int Qs[BQ * QSTR];        // 76032 B
    unsigned int Ks[2][BK * KSTR];     // 2 x 33792 B
    unsigned int Vs[BK * VSTR];        // 34816 B
    unsigned int Ps[BQ * PSTR];        // 39168 B  (tf32 bits of exp(p))
};
#define ATTN_SMEM ((int)sizeof(AttnSmem))   // 217600 B

__global__ __launch_bounds__(NTHR, 1)
void attn_tc_kernel(const float* __restrict__ q, float* __restrict__ out) {
    extern __shared__ char smraw[];
    AttnSmem* sm = (AttnSmem*)smraw;

    const int head = blockIdx.y;
    const int q0 = blockIdx.x * BQ;
    const int tid = threadIdx.x;
    const int lane = tid & 31;
    const int w = tid >> 5;          // 0..8
    const int g = lane >> 2;
    const int tg = lane & 3;
    const int wq = w * 16;           // q-row base for this warp
    const int r0 = wq + g;
    const int r1 = wq + g + 8;

    const unsigned int smem_base = (unsigned int)__cvta_generic_to_shared(sm);
    const unsigned int ks_base0 = smem_base + (unsigned int)((char*)sm->Ks[0] - (char*)sm);
    const unsigned int ks_base1 = smem_base + (unsigned int)((char*)sm->Ks[1] - (char*)sm);
    const unsigned int vs_base  = smem_base + (unsigned int)((char*)sm->Vs - (char*)sm);

    const bool loader = tid < 256;
    const int lr = tid >> 2;            // 0..63
    const int lc = (tid & 3) * 32;

    // ---- load Q tile (pre-rounded, pre-scaled tf32 bits) ----
    {
        const int r = tid >> 1;          // 0..143
        const int cbase = (tid & 1) * 64;
        const int srow = q0 + r;
        const bool valid = srow < S_TOK;
        const float* src = q + (size_t)srow * DIM + head * HD;
#pragma unroll
        for (int m2 = 0; m2 < 16; m2++) {
            int d = cbase + m2 * 4;
            float4 v = valid ? *(const float4*)(src + d) : make_float4(0.f, 0.f, 0.f, 0.f);
            *(float4*)&sm->Qs[r * QSTR + d] = v;
        }
    }

    float acc[16][4];
#pragma unroll
    for (int nf = 0; nf < 16; nf++)
#pragma unroll
        for (int j = 0; j < 4; j++) acc[nf][j] = 0.f;

    float m0 = -1e30f, m1 = -1e30f, l0 = 0.f, l1 = 0.f;

    const int NT = (L_TOT + BK - 1) / BK;  // 171

    // prologue: K(0) -> buffer 0
    if (loader) {
        const int kidx = min(lr, L_TOT - 1);
        const float* src = g_ck + (size_t)kidx * DIM + head * HD + lc;
#pragma unroll
        for (int i = 0; i < 8; i++)
            cp16(ks_base0 + (lr * KSTR + lc + i * 4) * 4, src + i * 4);
    }
    cp_commit();

    for (int t = 0; t < NT; t++) {
        const int kbase = t * BK;
        const unsigned int* Kbuf = sm->Ks[t & 1];

        // issue V(t) and K(t+1) (other K buffer)
        if (loader) {
            const int vk = min(kbase + lr, L_TOT - 1);
            const float* vsrc = g_cv + (size_t)vk * DIM + head * HD + lc;
#pragma unroll
            for (int i = 0; i < 8; i++)
                cp16(vs_base + (lr * VSTR + lc + i * 4) * 4, vsrc + i * 4);
        }
        cp_commit();
        if (loader) {
            const int kk = min(min(t + 1, NT - 1) * BK + lr, L_TOT - 1);
            const float* ksrc = g_ck + (size_t)kk * DIM + head * HD + lc;
            const unsigned int kb = ((t + 1) & 1) ? ks_base1 : ks_base0;
#pragma unroll
            for (int i = 0; i < 8; i++)
                cp16(kb + (lr * KSTR + lc + i * 4) * 4, ksrc + i * 4);
        }
        cp_commit();

        cp_wait<2>();      // K(t) complete
        __syncthreads();   // B1: K(t) visible; prev-iter Vs/Ps reads done

        // ---- scores: warp = 16q x 64k (base-2 domain, pre-scaled) ----
        float sc[8][4];
#pragma unroll
        for (int nf = 0; nf < 8; nf++)
#pragma unroll
            for (int j = 0; j < 4; j++) sc[nf][j] = 0.f;

#pragma unroll 4
        for (int kf = 0; kf < 16; kf++) {
            const int kc = kf * 8;
            unsigned int a0 = sm->Qs[r0 * QSTR + kc + tg];
            unsigned int a1 = sm->Qs[r1 * QSTR + kc + tg];
            unsigned int a2 = sm->Qs[r0 * QSTR + kc + tg + 4];
            unsigned int a3 = sm->Qs[r1 * QSTR + kc + tg + 4];
#pragma unroll
            for (int nf = 0; nf < 8; nf++) {
                unsigned int b0 = Kbuf[(nf * 8 + g) * KSTR + kc + tg];
                unsigned int b1 = Kbuf[(nf * 8 + g) * KSTR + kc + tg + 4];
                mma_tf32(sc[nf], a0, a1, a2, a3, b0, b1);
            }
        }

        // ---- mask tail tile ----
        if (kbase + BK > L_TOT) {
#pragma unroll
            for (int nf = 0; nf < 8; nf++) {
                const int c0 = kbase + nf * 8 + 2 * tg;
                if (c0 >= L_TOT)     { sc[nf][0] = -1e30f; sc[nf][2] = -1e30f; }
                if (c0 + 1 >= L_TOT) { sc[nf][1] = -1e30f; sc[nf][3] = -1e30f; }
            }
        }

        // ---- in-register softmax (rows r0, r1) ----
        float mx0 = -1e30f, mx1 = -1e30f;
#pragma unroll
        for (int nf = 0; nf < 8; nf++) {
            mx0 = fmaxf(mx0, fmaxf(sc[nf][0], sc[nf][1]));
            mx1 = fmaxf(mx1, fmaxf(sc[nf][2], sc[nf][3]));
        }
        mx0 = fmaxf(mx0, __shfl_xor_sync(0xffffffffu, mx0, 1));
        mx0 = fmaxf(mx0, __shfl_xor_sync(0xffffffffu, mx0, 2));
        mx1 = fmaxf(mx1, __shfl_xor_sync(0xffffffffu, mx1, 1));
        mx1 = fmaxf(mx1, __shfl_xor_sync(0xffffffffu, mx1, 2));
        const float mn0 = fmaxf(m0, mx0);
        const float mn1 = fmaxf(m1, mx1);
        const float al0 = exp2f(m0 - mn0);
        const float al1 = exp2f(m1 - mn1);

        float s0 = 0.f, s1 = 0.f;
#pragma unroll
        for (int nf = 0; nf < 8; nf++) {
            const float p00 = exp2f(sc[nf][0] - mn0);
            const float p01 = exp2f(sc[nf][1] - mn0);
            const float p10 = exp2f(sc[nf][2] - mn1);
            const float p11 = exp2f(sc[nf][3] - mn1);
            s0 += p00 + p01;
            s1 += p10 + p11;
            const int col = nf * 8 + 2 * tg;
            *(uint2*)&sm->Ps[r0 * PSTR + col] = make_uint2(f2tf(p00), f2tf(p01));
            *(uint2*)&sm->Ps[r1 * PSTR + col] = make_uint2(f2tf(p10), f2tf(p11));
        }
        s0 += __shfl_xor_sync(0xffffffffu, s0, 1);
        s0 += __shfl_xor_sync(0xffffffffu, s0, 2);
        s1 += __shfl_xor_sync(0xffffffffu, s1, 1);
        s1 += __shfl_xor_sync(0xffffffffu, s1, 2);
        l0 = l0 * al0 + s0;
        l1 = l1 * al1 + s1;
        m0 = mn0;
        m1 = mn1;

        __syncwarp();      // P (own rows) visible within the warp

        // rescale accumulators
#pragma unroll
        for (int nf = 0; nf < 16; nf++) {
            acc[nf][0] *= al0; acc[nf][1] *= al0;
            acc[nf][2] *= al1; acc[nf][3] *= al1;
        }

        cp_wait<1>();      // V(t) complete (K(t+1) may remain in flight)
        __syncthreads();   // B2: Vs visible to all warps

        // ---- PV: warp = 16q x 128hd over 64 k ----
        {
            const unsigned int* Pu = sm->Ps;
#pragma unroll 2
            for (int kf = 0; kf < 8; kf++) {
                const int kc = kf * 8;
                unsigned int a0 = Pu[r0 * PSTR + kc + tg];
                unsigned int a1 = Pu[r1 * PSTR + kc + tg];
                unsigned int a2 = Pu[r0 * PSTR + kc + tg + 4];
                unsigned int a3 = Pu[r1 * PSTR + kc + tg + 4];
#pragma unroll
                for (int nf = 0; nf < 16; nf++) {
                    unsigned int b0 = sm->Vs[(kc + tg) * VSTR + nf * 8 + g];
                    unsigned int b1 = sm->Vs[(kc + tg + 4) * VSTR + nf * 8 + g];
                    mma_tf32(acc[nf], a0, a1, a2, a3, b0, b1);
                }
            }
        }
        __syncthreads();   // B3: Vs/Ps free for next iteration
    }

    // ---- epilogue (l in registers) ----
    {
        const float inv0 = 1.0f / l0;
        const float inv1 = 1.0f / l1;
        const int row0 = q0 + r0;
        const int row1 = q0 + r1;
#pragma unroll
        for (int nf = 0; nf < 16; nf++) {
            const int col = head * HD + nf * 8 + 2 * tg;
            if (row0 < S_TOK)
                *(float2*)(out + (size_t)row0 * DIM + col) =
                    make_float2(acc[nf][0] * inv0, acc[nf][1] * inv0);
            if (row1 < S_TOK)
                *(float2*)(out + (size_t)row1 * DIM + col) =
                    make_float2(acc[nf][2] * inv1, acc[nf][3] * inv1);
        }
    }
}

// ---------------------------------------------------------------------------
extern "C" void kernel_launch(void* const* d_in, const int* in_sizes, int n_in,
                              void* d_out, int out_size) {
    (void)in_sizes; (void)n_in; (void)out_size;
    const float* x    = (const float*)d_in[0];
    const float* wq   = (const float*)d_in[1];
    const float* bq   = (const float*)d_in[2];
    const float* wk   = (const float*)d_in[3];
    const float* bk   = (const float*)d_in[4];
    const float* wv   = (const float*)d_in[5];
    const float* bv   = (const float*)d_in[6];
    const float* wo   = (const float*)d_in[7];
    const float* bo   = (const float*)d_in[8];
    const float* gq   = (const float*)d_in[9];
    const float* gk   = (const float*)d_in[10];
    const float* fcos = (const float*)d_in[11];
    const float* fsin = (const float*)d_in[12];
    const float* ck   = (const float*)d_in[13];
    const float* cvv  = (const float*)d_in[14];

    float *q, *k, *o, *gck;
    cudaGetSymbolAddress((void**)&q, g_q);
    cudaGetSymbolAddress((void**)&k, g_k);
    cudaGetSymbolAddress((void**)&o, g_o);
    cudaGetSymbolAddress((void**)&gck, g_ck);

    cudaFuncSetAttribute(attn_tc_kernel, cudaFuncAttributeMaxDynamicSharedMemorySize,
                         ATTN_SMEM);

    // 1. preround cache K/V into unified tf32 scratch
    preround_kernel<<<1024, 256>>>(ck, cvv);

    // 2. fused Q/K/V projections (V rounds straight into g_cv tail)
    dim3 qkvgrid(DIM / 128, (S_TOK + 127) / 128, 3);  // (12, 13, 3)
    gemm_qkv_kernel<<<qkvgrid, 256>>>(x, wq, bq, wk, bk, wv, bv, S_TOK);

    // 3. norm + rope: Q scaled to base-2 score domain; K appended to g_ck tail
    norm_rope_kernel<<<S_TOK, 256>>>(q, q, gq, fcos, fsin, SCALE_LOG2E);
    norm_rope_kernel<<<S_TOK, 256>>>(k, gck + (size_t)CUR * DIM, gk, fcos, fsin, 1.0f);

    // 4. attention (132 blocks, single wave)
    dim3 agrid((S_TOK + BQ - 1) / BQ, NH);  // (11, 12)
    attn_tc_kernel<<<agrid, NTHR, ATTN_SMEM>>>(q, o);

    // 5. output projection
    dim3 ogrid(DIM / 128, (S_TOK + 127) / 128);  // (12, 13)
    gemm_out_kernel<<<ogrid, 256>>>(o, wo, bo, (float*)d_out, S_TOK);
}

// round 7
// speedup vs baseline: 2.3932x; 1.9657x over previous
#include <cuda_runtime.h>
#include <cuda_fp16.h>
#include <math.h>

// Problem constants (fixed by setup_inputs)
#define DIM   1536
#define S_TOK 1560
#define NH    12
#define HD    128
#define CUR   9360          // current_start
#define L_TOT 10920         // KV window length (w0 = 0)
#define W_GRID 52
#define SCALE_LOG2E 0.12751776466576712f    // (1/sqrt(128)) * log2(e)

// Scratch (allocation-free: __device__ globals)
__device__ float  g_q[S_TOK * DIM];      // raw Q projection (f32)
__device__ float  g_k[S_TOK * DIM];      // raw K projection (f32)
__device__ float  g_o[S_TOK * DIM];      // attention output (f32)
__device__ __half g_qh[S_TOK * DIM];     // normed+rope+scaled Q (fp16)
__device__ __half g_ckh[L_TOT * DIM];    // K window [token][head][hd] fp16
__device__ __half g_cvh[L_TOT * DIM];    // V window [token][head][hd] fp16

__device__ __forceinline__ unsigned pack_h2(float a, float b) {
    __half2 h = __floats2half2_rn(a, b);
    return *(unsigned*)&h;
}

__device__ __forceinline__ void mma_f16(float c[4], unsigned a0, unsigned a1,
                                        unsigned a2, unsigned a3,
                                        unsigned b0, unsigned b1) {
    asm("mma.sync.aligned.m16n8k16.row.col.f32.f16.f16.f32 "
        "{%0,%1,%2,%3}, {%4,%5,%6,%7}, {%8,%9}, {%0,%1,%2,%3};"
        : "+f"(c[0]), "+f"(c[1]), "+f"(c[2]), "+f"(c[3])
        : "r"(a0), "r"(a1), "r"(a2), "r"(a3), "r"(b0), "r"(b1));
}

__device__ __forceinline__ void ldsm4(unsigned& d0, unsigned& d1, unsigned& d2,
                                      unsigned& d3, unsigned addr) {
    asm volatile("ldmatrix.sync.aligned.m8n8.x4.shared.b16 {%0,%1,%2,%3}, [%4];"
                 : "=r"(d0), "=r"(d1), "=r"(d2), "=r"(d3) : "r"(addr));
}
__device__ __forceinline__ void ldsm4t(unsigned& d0, unsigned& d1, unsigned& d2,
                                       unsigned& d3, unsigned addr) {
    asm volatile("ldmatrix.sync.aligned.m8n8.x4.trans.shared.b16 {%0,%1,%2,%3}, [%4];"
                 : "=r"(d0), "=r"(d1), "=r"(d2), "=r"(d3) : "r"(addr));
}

__device__ __forceinline__ void cp16(unsigned s_addr, const void* gptr) {
    asm volatile("cp.async.ca.shared.global [%0], [%1], 16;\n" :: "r"(s_addr), "l"(gptr));
}
__device__ __forceinline__ void cp_commit() { asm volatile("cp.async.commit_group;\n"); }
template <int N> __device__ __forceinline__ void cp_wait() {
    asm volatile("cp.async.wait_group %0;\n" :: "n"(N));
}

// ---------------------------------------------------------------------------
// Preround: f32 cache K/V -> fp16 scratch (first CUR tokens)
// ---------------------------------------------------------------------------
__global__ __launch_bounds__(256)
void preround_kernel(const float* __restrict__ ck, const float* __restrict__ cv) {
    const size_t n = (size_t)CUR * DIM;
    size_t i = ((size_t)blockIdx.x * 256 + threadIdx.x) * 4;
    const size_t stride = (size_t)gridDim.x * 256 * 4;
    for (; i < n; i += stride) {
        float4 a = *(const float4*)(ck + i);
        float4 b = *(const float4*)(cv + i);
        *(uint2*)(g_ckh + i) = make_uint2(pack_h2(a.x, a.y), pack_h2(a.z, a.w));
        *(uint2*)(g_cvh + i) = make_uint2(pack_h2(b.x, b.y), pack_h2(b.z, b.w));
    }
}

// ---------------------------------------------------------------------------
// fp16 GEMM: C = A @ B^T + bias. 128x128 tile, BK=32, 8 warps, m16n8k16.
// If Ch != nullptr, write fp16 to Ch instead of f32 to Cf.
// ---------------------------------------------------------------------------
#define GSTRH 40   // half-stride: 20 words mod 32 = 20 -> conflict-free frags

__device__ __forceinline__ void gemm_body(const float* __restrict__ A,
                                          const float* __restrict__ B,
                                          const float* __restrict__ bias,
                                          float* Cf, __half* Ch, int M) {
    __shared__ __half As[128 * GSTRH];
    __shared__ __half Bs[128 * GSTRH];
    const int tid = threadIdx.x;
    const int m0 = blockIdx.y * 128;
    const int n0 = blockIdx.x * 128;
    const int lane = tid & 31;
    const int w = tid >> 5;
    const int g = lane >> 2;
    const int tg = lane & 3;
    const int wy = w >> 1;
    const int wx = w & 1;
    const int r = tid >> 1;
    const int kloc = (tid & 1) * 16;

    float acc[2][8][4];
#pragma unroll
    for (int mf = 0; mf < 2; mf++)
#pragma unroll
        for (int nf = 0; nf < 8; nf++)
#pragma unroll
            for (int j = 0; j < 4; j++) acc[mf][nf][j] = 0.f;

    const bool avalid = (m0 + r) < M;
    const float* pa = A + (size_t)(m0 + r) * DIM + kloc;
    const float* pb = B + (size_t)(n0 + r) * DIM + kloc;
    const float4 z4 = make_float4(0.f, 0.f, 0.f, 0.f);

    for (int k0 = 0; k0 < DIM; k0 += 32) {
        {
            float4 f0 = avalid ? *(const float4*)(pa + k0) : z4;
            float4 f1 = avalid ? *(const float4*)(pa + k0 + 4) : z4;
            float4 f2 = avalid ? *(const float4*)(pa + k0 + 8) : z4;
            float4 f3 = avalid ? *(const float4*)(pa + k0 + 12) : z4;
            *(uint4*)&As[r * GSTRH + kloc] =
                make_uint4(pack_h2(f0.x, f0.y), pack_h2(f0.z, f0.w),
                           pack_h2(f1.x, f1.y), pack_h2(f1.z, f1.w));
            *(uint4*)&As[r * GSTRH + kloc + 8] =
                make_uint4(pack_h2(f2.x, f2.y), pack_h2(f2.z, f2.w),
                           pack_h2(f3.x, f3.y), pack_h2(f3.z, f3.w));
        }
        {
            float4 f0 = *(const float4*)(pb + k0);
            float4 f1 = *(const float4*)(pb + k0 + 4);
            float4 f2 = *(const float4*)(pb + k0 + 8);
            float4 f3 = *(const float4*)(pb + k0 + 12);
            *(uint4*)&Bs[r * GSTRH + kloc] =
                make_uint4(pack_h2(f0.x, f0.y), pack_h2(f0.z, f0.w),
                           pack_h2(f1.x, f1.y), pack_h2(f1.z, f1.w));
            *(uint4*)&Bs[r * GSTRH + kloc + 8] =
                make_uint4(pack_h2(f2.x, f2.y), pack_h2(f2.z, f2.w),
                           pack_h2(f3.x, f3.y), pack_h2(f3.z, f3.w));
        }
        __syncthreads();
#pragma unroll
        for (int kc = 0; kc < 32; kc += 16) {
            unsigned a[2][4];
#pragma unroll
            for (int mf = 0; mf < 2; mf++) {
                const int row = wy * 32 + mf * 16 + g;
                a[mf][0] = *(const unsigned*)&As[row * GSTRH + kc + 2 * tg];
                a[mf][1] = *(const unsigned*)&As[(row + 8) * GSTRH + kc + 2 * tg];
                a[mf][2] = *(const unsigned*)&As[row * GSTRH + kc + 8 + 2 * tg];
                a[mf][3] = *(const unsigned*)&As[(row + 8) * GSTRH + kc + 8 + 2 * tg];
            }
#pragma unroll
            for (int nf = 0; nf < 8; nf++) {
                const int brow = wx * 64 + nf * 8 + g;
                unsigned b0 = *(const unsigned*)&Bs[brow * GSTRH + kc + 2 * tg];
                unsigned b1 = *(const unsigned*)&Bs[brow * GSTRH + kc + 8 + 2 * tg];
                mma_f16(acc[0][nf], a[0][0], a[0][1], a[0][2], a[0][3], b0, b1);
                mma_f16(acc[1][nf], a[1][0], a[1][1], a[1][2], a[1][3], b0, b1);
            }
        }
        __syncthreads();
    }

#pragma unroll
    for (int mf = 0; mf < 2; mf++) {
        const int row = m0 + wy * 32 + mf * 16 + g;
#pragma unroll
        for (int nf = 0; nf < 8; nf++) {
            const int col = n0 + wx * 64 + nf * 8 + 2 * tg;
            const float b0 = bias[col], b1 = bias[col + 1];
            float v00 = acc[mf][nf][0] + b0, v01 = acc[mf][nf][1] + b1;
            float v10 = acc[mf][nf][2] + b0, v11 = acc[mf][nf][3] + b1;
            if (Ch) {
                if (row < M)
                    *(unsigned*)(Ch + (size_t)row * DIM + col) = pack_h2(v00, v01);
                if (row + 8 < M)
                    *(unsigned*)(Ch + (size_t)(row + 8) * DIM + col) = pack_h2(v10, v11);
            } else {
                if (row < M)
                    *(float2*)(Cf + (size_t)row * DIM + col) = make_float2(v00, v01);
                if (row + 8 < M)
                    *(float2*)(Cf + (size_t)(row + 8) * DIM + col) = make_float2(v10, v11);
            }
        }
    }
}

__global__ __launch_bounds__(256, 2)
void gemm_qkv_kernel(const float* __restrict__ A,
                     const float* __restrict__ wq, const float* __restrict__ bq,
                     const float* __restrict__ wk, const float* __restrict__ bk,
                     const float* __restrict__ wv, const float* __restrict__ bv,
                     int M) {
    if (blockIdx.z == 0)      gemm_body(A, wq, bq, g_q, nullptr, M);
    else if (blockIdx.z == 1) gemm_body(A, wk, bk, g_k, nullptr, M);
    else                      gemm_body(A, wv, bv, nullptr, g_cvh + (size_t)CUR * DIM, M);
}

__global__ __launch_bounds__(256, 2)
void gemm_out_kernel(const float* __restrict__ A, const float* __restrict__ B,
                     const float* __restrict__ bias, float* __restrict__ C, int M) {
    gemm_body(A, B, bias, C, nullptr, M);
}

// ---------------------------------------------------------------------------
// rmsnorm + RoPE, scaled by oscale, fp16 output
// ---------------------------------------------------------------------------
__global__ __launch_bounds__(256)
void norm_rope_kernel(const float* __restrict__ src, __half* __restrict__ dst,
                      const float* __restrict__ g,
                      const float* __restrict__ fcos, const float* __restrict__ fsin,
                      float oscale) {
    const int s = blockIdx.x;
    const float* row = src + (size_t)s * DIM;
    __half* orow = dst + (size_t)s * DIM;
    __shared__ float red[256];

    float ss = 0.f;
    for (int i = threadIdx.x; i < DIM; i += 256) {
        float v = row[i];
        ss += v * v;
    }
    red[threadIdx.x] = ss;
    __syncthreads();
    for (int off = 128; off > 0; off >>= 1) {
        if (threadIdx.x < off) red[threadIdx.x] += red[threadIdx.x + off];
        __syncthreads();
    }
    const float scale = rsqrtf(red[0] * (1.0f / DIM) + 1e-6f);

    const int hh = s / W_GRID;
    const int ww = s % W_GRID;
    for (int p = threadIdx.x; p < NH * 64; p += 256) {
        const int head = p >> 6;
        const int c = p & 63;
        const int trow = (c < 22) ? 6 : ((c < 43) ? hh : ww);
        const float cv = fcos[trow * 64 + c];
        const float sv = fsin[trow * 64 + c];
        const int base = head * HD + 2 * c;
        const float xr = row[base] * scale * g[base];
        const float xi = row[base + 1] * scale * g[base + 1];
        *(unsigned*)(orow + base) =
            pack_h2((xr * cv - xi * sv) * oscale, (xr * sv + xi * cv) * oscale);
    }
}

// ---------------------------------------------------------------------------
// fp16 flash attention, m16n8k16 + ldmatrix. BQ=144 x BK=64, 9 warps.
// Grid 11x12 = 132 blocks (one wave). Warp owns 16 q-rows end-to-end.
// K double-buffered; V single buffer; in-register softmax (base-2 domain).
// Strides: Q/K/V 136 halfs (68 words ≡ 4 mod 32), P 72 halfs (36 ≡ 4 mod 32)
//   -> all LDSM phases + P stores conflict-free.
// ---------------------------------------------------------------------------
#define BQ 144
#define BK 64
#define QSH 136
#define KSH 136
#define VSH 136
#define PSH 72
#define NTHR 288

struct __align__(16) AttnSmem {
    __half Qs[BQ * QSH];        // 39168 B
    __half Ks[2][BK * KSH];     // 2 x 17408 B
    __half Vs[BK * VSH];        // 17408 B
    __half Ps[BQ * PSH];        // 20736 B
};
#define ATTN_SMEM ((int)sizeof(AttnSmem))   // 112128 B

__global__ __launch_bounds__(NTHR, 1)
void attn_tc_kernel(const __half* __restrict__ qh, float* __restrict__ out) {
    extern __shared__ char smraw[];
    AttnSmem* sm = (AttnSmem*)smraw;

    const int head = blockIdx.y;
    const int q0 = blockIdx.x * BQ;
    const int tid = threadIdx.x;
    const int lane = tid & 31;
    const int w = tid >> 5;          // 0..8
    const int g = lane >> 2;
    const int tg = lane & 3;
    const int wq = w * 16;
    const int r0 = wq + g;
    const int r1 = wq + g + 8;

    const unsigned smem_base = (unsigned)__cvta_generic_to_shared(sm);
    const unsigned qs_b = smem_base;
    const unsigned ks_b0 = smem_base + (unsigned)((char*)sm->Ks[0] - (char*)sm);
    const unsigned ks_b1 = smem_base + (unsigned)((char*)sm->Ks[1] - (char*)sm);
    const unsigned vs_b  = smem_base + (unsigned)((char*)sm->Vs - (char*)sm);
    const unsigned ps_b  = smem_base + (unsigned)((char*)sm->Ps - (char*)sm);

    // ldmatrix per-lane address components (byte offsets)
    const unsigned qa_off = qs_b + (((wq + (lane & 15)) * QSH + (lane >> 4) * 8) * 2);
    const unsigned kb_off = ((((lane >> 4) & 1) * 8 + (lane & 7)) * KSH +
                             ((lane >> 3) & 1) * 8) * 2;
    const unsigned pa_off = ps_b + (((wq + (lane & 15)) * PSH + (lane >> 4) * 8) * 2);
    const unsigned vb_off = vs_b + (((((lane >> 3) & 1) * 8 + (lane & 7)) * VSH +
                                     ((lane >> 4) & 1) * 8) * 2);

    // loaders (threads 0..255): K/V tiles, 4 x 16B each
    const bool loader = tid < 256;
    const int lr = tid >> 2;            // 0..63
    const int lc = (tid & 3) * 32;      // half col base (64B)

    // ---- load Q tile (fp16, pre-scaled), zero-pad tail rows ----
    {
        const int r = tid >> 1;          // 0..143
        const int cb = (tid & 1) * 64;
        const int srow = q0 + r;
        const bool valid = srow < S_TOK;
        const __half* src = qh + (size_t)srow * DIM + head * HD + cb;
        const uint4 z = make_uint4(0, 0, 0, 0);
#pragma unroll
        for (int m2 = 0; m2 < 8; m2++) {
            uint4 v = valid ? *(const uint4*)(src + m2 * 8) : z;
            *(uint4*)&sm->Qs[r * QSH + cb + m2 * 8] = v;
        }
    }

    float acc[16][4];
#pragma unroll
    for (int nf = 0; nf < 16; nf++)
#pragma unroll
        for (int j = 0; j < 4; j++) acc[nf][j] = 0.f;

    float m0 = -1e30f, m1 = -1e30f, l0 = 0.f, l1 = 0.f;

    const int NT = (L_TOT + BK - 1) / BK;  // 171

    // prologue: K(0) -> buffer 0
    if (loader) {
        const int kidx = min(lr, L_TOT - 1);
        const __half* src = g_ckh + (size_t)kidx * DIM + head * HD + lc;
#pragma unroll
        for (int i = 0; i < 4; i++)
            cp16(ks_b0 + (lr * KSH + lc + i * 8) * 2, src + i * 8);
    }
    cp_commit();

    for (int t = 0; t < NT; t++) {
        const int kbase = t * BK;
        const unsigned ksb = (t & 1) ? ks_b1 : ks_b0;

        // issue V(t), then K(t+1)
        if (loader) {
            const int vk = min(kbase + lr, L_TOT - 1);
            const __half* vsrc = g_cvh + (size_t)vk * DIM + head * HD + lc;
#pragma unroll
            for (int i = 0; i < 4; i++)
                cp16(vs_b + (lr * VSH + lc + i * 8) * 2, vsrc + i * 8);
        }
        cp_commit();
        if (loader) {
            const int kk = min(min(t + 1, NT - 1) * BK + lr, L_TOT - 1);
            const __half* ksrc = g_ckh + (size_t)kk * DIM + head * HD + lc;
            const unsigned kb = ((t + 1) & 1) ? ks_b1 : ks_b0;
#pragma unroll
            for (int i = 0; i < 4; i++)
                cp16(kb + (lr * KSH + lc + i * 8) * 2, ksrc + i * 8);
        }
        cp_commit();

        cp_wait<2>();      // K(t) complete
        __syncthreads();   // B1

        // ---- scores: warp = 16q x 64k, 8 kf x 8 nf mmas ----
        float sc[8][4];
#pragma unroll
        for (int nf = 0; nf < 8; nf++)
#pragma unroll
            for (int j = 0; j < 4; j++) sc[nf][j] = 0.f;

#pragma unroll
        for (int kf = 0; kf < 8; kf++) {
            unsigned a0, a1, a2, a3;
            ldsm4(a0, a1, a2, a3, qa_off + kf * 32);
#pragma unroll
            for (int nfp = 0; nfp < 4; nfp++) {
                unsigned b00, b01, b10, b11;
                ldsm4(b00, b01, b10, b11, ksb + nfp * (16 * KSH * 2) + kb_off + kf * 32);
                mma_f16(sc[2 * nfp],     a0, a1, a2, a3, b00, b01);
                mma_f16(sc[2 * nfp + 1], a0, a1, a2, a3, b10, b11);
            }
        }

        // ---- mask tail tile ----
        if (kbase + BK > L_TOT) {
#pragma unroll
            for (int nf = 0; nf < 8; nf++) {
                const int c0 = kbase + nf * 8 + 2 * tg;
                if (c0 >= L_TOT)     { sc[nf][0] = -1e30f; sc[nf][2] = -1e30f; }
                if (c0 + 1 >= L_TOT) { sc[nf][1] = -1e30f; sc[nf][3] = -1e30f; }
            }
        }

        // ---- in-register softmax (rows r0, r1), base-2 domain ----
        float mx0 = -1e30f, mx1 = -1e30f;
#pragma unroll
        for (int nf = 0; nf < 8; nf++) {
            mx0 = fmaxf(mx0, fmaxf(sc[nf][0], sc[nf][1]));
            mx1 = fmaxf(mx1, fmaxf(sc[nf][2], sc[nf][3]));
        }
        mx0 = fmaxf(mx0, __shfl_xor_sync(0xffffffffu, mx0, 1));
        mx0 = fmaxf(mx0, __shfl_xor_sync(0xffffffffu, mx0, 2));
        mx1 = fmaxf(mx1, __shfl_xor_sync(0xffffffffu, mx1, 1));
        mx1 = fmaxf(mx1, __shfl_xor_sync(0xffffffffu, mx1, 2));
        const float mn0 = fmaxf(m0, mx0);
        const float mn1 = fmaxf(m1, mx1);
        const float al0 = exp2f(m0 - mn0);
        const float al1 = exp2f(m1 - mn1);

        float s0 = 0.f, s1 = 0.f;
#pragma unroll
        for (int nf = 0; nf < 8; nf++) {
            const float p00 = exp2f(sc[nf][0] - mn0);
            const float p01 = exp2f(sc[nf][1] - mn0);
            const float p10 = exp2f(sc[nf][2] - mn1);
            const float p11 = exp2f(sc[nf][3] - mn1);
            s0 += p00 + p01;
            s1 += p10 + p11;
            const int col = nf * 8 + 2 * tg;
            *(unsigned*)&sm->Ps[r0 * PSH + col] = pack_h2(p00, p01);
            *(unsigned*)&sm->Ps[r1 * PSH + col] = pack_h2(p10, p11);
        }
        s0 += __shfl_xor_sync(0xffffffffu, s0, 1);
        s0 += __shfl_xor_sync(0xffffffffu, s0, 2);
        s1 += __shfl_xor_sync(0xffffffffu, s1, 1);
        s1 += __shfl_xor_sync(0xffffffffu, s1, 2);
        l0 = l0 * al0 + s0;
        l1 = l1 * al1 + s1;
        m0 = mn0;
        m1 = mn1;

        __syncwarp();      // own-row P visible to this warp's ldmatrix

        // rescale accumulators
#pragma unroll
        for (int nf = 0; nf < 16; nf++) {
            acc[nf][0] *= al0; acc[nf][1] *= al0;
            acc[nf][2] *= al1; acc[nf][3] *= al1;
        }

        cp_wait<1>();      // V(t) complete
        __syncthreads();   // B2: Vs visible

        // ---- PV: warp = 16q x 128hd over 64 k, 4 kf x 16 nf mmas ----
#pragma unroll
        for (int kf = 0; kf < 4; kf++) {
            unsigned a0, a1, a2, a3;
            ldsm4(a0, a1, a2, a3, pa_off + kf * 32);
#pragma unroll
            for (int nfp = 0; nfp < 8; nfp++) {
                unsigned b00, b01, b10, b11;
                ldsm4t(b00, b01, b10, b11,
                       vb_off + kf * (16 * VSH * 2) + nfp * 32);
                mma_f16(acc[2 * nfp],     a0, a1, a2, a3, b00, b01);
                mma_f16(acc[2 * nfp + 1], a0, a1, a2, a3, b10, b11);
            }
        }
        __syncthreads();   // B3: Vs/Ps free
    }

    // ---- epilogue ----
    {
        const float inv0 = 1.0f / l0;
        const float inv1 = 1.0f / l1;
        const int row0 = q0 + r0;
        const int row1 = q0 + r1;
#pragma unroll
        for (int nf = 0; nf < 16; nf++) {
            const int col = head * HD + nf * 8 + 2 * tg;
            if (row0 < S_TOK)
                *(float2*)(out + (size_t)row0 * DIM + col) =
                    make_float2(acc[nf][0] * inv0, acc[nf][1] * inv0);
            if (row1 < S_TOK)
                *(float2*)(out + (size_t)row1 * DIM + col) =
                    make_float2(acc[nf][2] * inv1, acc[nf][3] * inv1);
        }
    }
}

// ---------------------------------------------------------------------------
extern "C" void kernel_launch(void* const* d_in, const int* in_sizes, int n_in,
                              void* d_out, int out_size) {
    (void)in_sizes; (void)n_in; (void)out_size;
    const float* x    = (const float*)d_in[0];
    const float* wq   = (const float*)d_in[1];
    const float* bq   = (const float*)d_in[2];
    const float* wk   = (const float*)d_in[3];
    const float* bk   = (const float*)d_in[4];
    const float* wv   = (const float*)d_in[5];
    const float* bv   = (const float*)d_in[6];
    const float* wo   = (const float*)d_in[7];
    const float* bo   = (const float*)d_in[8];
    const float* gq   = (const float*)d_in[9];
    const float* gk   = (const float*)d_in[10];
    const float* fcos = (const float*)d_in[11];
    const float* fsin = (const float*)d_in[12];
    const float* ck   = (const float*)d_in[13];
    const float* cvv  = (const float*)d_in[14];

    float *q, *k, *o;
    __half *qh, *ckh;
    cudaGetSymbolAddress((void**)&q, g_q);
    cudaGetSymbolAddress((void**)&k, g_k);
    cudaGetSymbolAddress((void**)&o, g_o);
    cudaGetSymbolAddress((void**)&qh, g_qh);
    cudaGetSymbolAddress((void**)&ckh, g_ckh);

    cudaFuncSetAttribute(attn_tc_kernel, cudaFuncAttributeMaxDynamicSharedMemorySize,
                         ATTN_SMEM);

    // 1. preround cache K/V into fp16 scratch
    preround_kernel<<<1024, 256>>>(ck, cvv);

    // 2. fused Q/K/V projections (V written fp16 into g_cvh tail)
    dim3 qkvgrid(DIM / 128, (S_TOK + 127) / 128, 3);  // (12, 13, 3)
    gemm_qkv_kernel<<<qkvgrid, 256>>>(x, wq, bq, wk, bk, wv, bv, S_TOK);

    // 3. norm + rope: Q scaled to base-2 score domain -> g_qh; K -> g_ckh tail
    norm_rope_kernel<<<S_TOK, 256>>>(q, qh, gq, fcos, fsin, SCALE_LOG2E);
    norm_rope_kernel<<<S_TOK, 256>>>(k, ckh + (size_t)CUR * DIM, gk, fcos, fsin, 1.0f);

    // 4. attention (132 blocks, single wave)
    dim3 agrid((S_TOK + BQ - 1) / BQ, NH);  // (11, 12)
    attn_tc_kernel<<<agrid, NTHR, ATTN_SMEM>>>(qh, o);

    // 5. output projection
    dim3 ogrid(DIM / 128, (S_TOK + 127) / 128);  // (12, 13)
    gemm_out_kernel<<<ogrid, 256>>>(o, wo, bo, (float*)d_out, S_TOK);
}

// round 8
// speedup vs baseline: 2.5886x; 1.0816x over previous
#include <cuda_runtime.h>
#include <cuda_fp16.h>
#include <math.h>

// Problem constants (fixed by setup_inputs)
#define DIM   1536
#define S_TOK 1560
#define NH    12
#define HD    128
#define CUR   9360          // current_start
#define L_TOT 10920         // KV window length (w0 = 0)
#define W_GRID 52
#define SCALE_LOG2E 0.12751776466576712f    // (1/sqrt(128)) * log2(e)

// Scratch (allocation-free: __device__ globals)
__device__ float  g_q[S_TOK * DIM];      // raw Q projection (f32)
__device__ float  g_k[S_TOK * DIM];      // raw K projection (f32)
__device__ float  g_o[S_TOK * DIM];      // attention output (f32)
__device__ __half g_qh[S_TOK * DIM];     // normed+rope+scaled Q (fp16)
__device__ __half g_ckh[L_TOT * DIM];    // K window [token][head][hd] fp16
__device__ __half g_cvh[L_TOT * DIM];    // V window [token][head][hd] fp16

__device__ __forceinline__ unsigned pack_h2(float a, float b) {
    __half2 h = __floats2half2_rn(a, b);
    return *(unsigned*)&h;
}

__device__ __forceinline__ void mma_f16(float c[4], unsigned a0, unsigned a1,
                                        unsigned a2, unsigned a3,
                                        unsigned b0, unsigned b1) {
    asm("mma.sync.aligned.m16n8k16.row.col.f32.f16.f16.f32 "
        "{%0,%1,%2,%3}, {%4,%5,%6,%7}, {%8,%9}, {%0,%1,%2,%3};"
        : "+f"(c[0]), "+f"(c[1]), "+f"(c[2]), "+f"(c[3])
        : "r"(a0), "r"(a1), "r"(a2), "r"(a3), "r"(b0), "r"(b1));
}

__device__ __forceinline__ void ldsm4(unsigned& d0, unsigned& d1, unsigned& d2,
                                      unsigned& d3, unsigned addr) {
    asm volatile("ldmatrix.sync.aligned.m8n8.x4.shared.b16 {%0,%1,%2,%3}, [%4];"
                 : "=r"(d0), "=r"(d1), "=r"(d2), "=r"(d3) : "r"(addr));
}
__device__ __forceinline__ void ldsm4t(unsigned& d0, unsigned& d1, unsigned& d2,
                                       unsigned& d3, unsigned addr) {
    asm volatile("ldmatrix.sync.aligned.m8n8.x4.trans.shared.b16 {%0,%1,%2,%3}, [%4];"
                 : "=r"(d0), "=r"(d1), "=r"(d2), "=r"(d3) : "r"(addr));
}

__device__ __forceinline__ void cp16(unsigned s_addr, const void* gptr) {
    asm volatile("cp.async.ca.shared.global [%0], [%1], 16;\n" :: "r"(s_addr), "l"(gptr));
}
__device__ __forceinline__ void cp_commit() { asm volatile("cp.async.commit_group;\n"); }
template <int N> __device__ __forceinline__ void cp_wait() {
    asm volatile("cp.async.wait_group %0;\n" :: "n"(N));
}

// ---------------------------------------------------------------------------
// Preround: f32 cache K/V -> fp16 scratch (first CUR tokens)
// ---------------------------------------------------------------------------
__global__ __launch_bounds__(256)
void preround_kernel(const float* __restrict__ ck, const float* __restrict__ cv) {
    const size_t n = (size_t)CUR * DIM;
    size_t i = ((size_t)blockIdx.x * 256 + threadIdx.x) * 4;
    const size_t stride = (size_t)gridDim.x * 256 * 4;
    for (; i < n; i += stride) {
        float4 a = *(const float4*)(ck + i);
        float4 b = *(const float4*)(cv + i);
        *(uint2*)(g_ckh + i) = make_uint2(pack_h2(a.x, a.y), pack_h2(a.z, a.w));
        *(uint2*)(g_cvh + i) = make_uint2(pack_h2(b.x, b.y), pack_h2(b.z, b.w));
    }
}

// ---------------------------------------------------------------------------
// fp16 GEMM: C = A @ B^T + bias. 128x128 tile, BK=32, 8 warps, m16n8k16.
// ---------------------------------------------------------------------------
#define GSTRH 40

__device__ __forceinline__ void gemm_body(const float* __restrict__ A,
                                          const float* __restrict__ B,
                                          const float* __restrict__ bias,
                                          float* Cf, __half* Ch, int M) {
    __shared__ __half As[128 * GSTRH];
    __shared__ __half Bs[128 * GSTRH];
    const int tid = threadIdx.x;
    const int m0 = blockIdx.y * 128;
    const int n0 = blockIdx.x * 128;
    const int lane = tid & 31;
    const int w = tid >> 5;
    const int g = lane >> 2;
    const int tg = lane & 3;
    const int wy = w >> 1;
    const int wx = w & 1;
    const int r = tid >> 1;
    const int kloc = (tid & 1) * 16;

    float acc[2][8][4];
#pragma unroll
    for (int mf = 0; mf < 2; mf++)
#pragma unroll
        for (int nf = 0; nf < 8; nf++)
#pragma unroll
            for (int j = 0; j < 4; j++) acc[mf][nf][j] = 0.f;

    const bool avalid = (m0 + r) < M;
    const float* pa = A + (size_t)(m0 + r) * DIM + kloc;
    const float* pb = B + (size_t)(n0 + r) * DIM + kloc;
    const float4 z4 = make_float4(0.f, 0.f, 0.f, 0.f);

    for (int k0 = 0; k0 < DIM; k0 += 32) {
        {
            float4 f0 = avalid ? *(const float4*)(pa + k0) : z4;
            float4 f1 = avalid ? *(const float4*)(pa + k0 + 4) : z4;
            float4 f2 = avalid ? *(const float4*)(pa + k0 + 8) : z4;
            float4 f3 = avalid ? *(const float4*)(pa + k0 + 12) : z4;
            *(uint4*)&As[r * GSTRH + kloc] =
                make_uint4(pack_h2(f0.x, f0.y), pack_h2(f0.z, f0.w),
                           pack_h2(f1.x, f1.y), pack_h2(f1.z, f1.w));
            *(uint4*)&As[r * GSTRH + kloc + 8] =
                make_uint4(pack_h2(f2.x, f2.y), pack_h2(f2.z, f2.w),
                           pack_h2(f3.x, f3.y), pack_h2(f3.z, f3.w));
        }
        {
            float4 f0 = *(const float4*)(pb + k0);
            float4 f1 = *(const float4*)(pb + k0 + 4);
            float4 f2 = *(const float4*)(pb + k0 + 8);
            float4 f3 = *(const float4*)(pb + k0 + 12);
            *(uint4*)&Bs[r * GSTRH + kloc] =
                make_uint4(pack_h2(f0.x, f0.y), pack_h2(f0.z, f0.w),
                           pack_h2(f1.x, f1.y), pack_h2(f1.z, f1.w));
            *(uint4*)&Bs[r * GSTRH + kloc + 8] =
                make_uint4(pack_h2(f2.x, f2.y), pack_h2(f2.z, f2.w),
                           pack_h2(f3.x, f3.y), pack_h2(f3.z, f3.w));
        }
        __syncthreads();
#pragma unroll
        for (int kc = 0; kc < 32; kc += 16) {
            unsigned a[2][4];
#pragma unroll
            for (int mf = 0; mf < 2; mf++) {
                const int row = wy * 32 + mf * 16 + g;
                a[mf][0] = *(const unsigned*)&As[row * GSTRH + kc + 2 * tg];
                a[mf][1] = *(const unsigned*)&As[(row + 8) * GSTRH + kc + 2 * tg];
                a[mf][2] = *(const unsigned*)&As[row * GSTRH + kc + 8 + 2 * tg];
                a[mf][3] = *(const unsigned*)&As[(row + 8) * GSTRH + kc + 8 + 2 * tg];
            }
#pragma unroll
            for (int nf = 0; nf < 8; nf++) {
                const int brow = wx * 64 + nf * 8 + g;
                unsigned b0 = *(const unsigned*)&Bs[brow * GSTRH + kc + 2 * tg];
                unsigned b1 = *(const unsigned*)&Bs[brow * GSTRH + kc + 8 + 2 * tg];
                mma_f16(acc[0][nf], a[0][0], a[0][1], a[0][2], a[0][3], b0, b1);
                mma_f16(acc[1][nf], a[1][0], a[1][1], a[1][2], a[1][3], b0, b1);
            }
        }
        __syncthreads();
    }

#pragma unroll
    for (int mf = 0; mf < 2; mf++) {
        const int row = m0 + wy * 32 + mf * 16 + g;
#pragma unroll
        for (int nf = 0; nf < 8; nf++) {
            const int col = n0 + wx * 64 + nf * 8 + 2 * tg;
            const float b0 = bias[col], b1 = bias[col + 1];
            float v00 = acc[mf][nf][0] + b0, v01 = acc[mf][nf][1] + b1;
            float v10 = acc[mf][nf][2] + b0, v11 = acc[mf][nf][3] + b1;
            if (Ch) {
                if (row < M)
                    *(unsigned*)(Ch + (size_t)row * DIM + col) = pack_h2(v00, v01);
                if (row + 8 < M)
                    *(unsigned*)(Ch + (size_t)(row + 8) * DIM + col) = pack_h2(v10, v11);
            } else {
                if (row < M)
                    *(float2*)(Cf + (size_t)row * DIM + col) = make_float2(v00, v01);
                if (row + 8 < M)
                    *(float2*)(Cf + (size_t)(row + 8) * DIM + col) = make_float2(v10, v11);
            }
        }
    }
}

__global__ __launch_bounds__(256, 2)
void gemm_qkv_kernel(const float* __restrict__ A,
                     const float* __restrict__ wq, const float* __restrict__ bq,
                     const float* __restrict__ wk, const float* __restrict__ bk,
                     const float* __restrict__ wv, const float* __restrict__ bv,
                     int M) {
    if (blockIdx.z == 0)      gemm_body(A, wq, bq, g_q, nullptr, M);
    else if (blockIdx.z == 1) gemm_body(A, wk, bk, g_k, nullptr, M);
    else                      gemm_body(A, wv, bv, nullptr, g_cvh + (size_t)CUR * DIM, M);
}

__global__ __launch_bounds__(256, 2)
void gemm_out_kernel(const float* __restrict__ A, const float* __restrict__ B,
                     const float* __restrict__ bias, float* __restrict__ C, int M) {
    gemm_body(A, B, bias, C, nullptr, M);
}

// ---------------------------------------------------------------------------
// rmsnorm + RoPE, scaled by oscale, fp16 output
// ---------------------------------------------------------------------------
__global__ __launch_bounds__(256)
void norm_rope_kernel(const float* __restrict__ src, __half* __restrict__ dst,
                      const float* __restrict__ g,
                      const float* __restrict__ fcos, const float* __restrict__ fsin,
                      float oscale) {
    const int s = blockIdx.x;
    const float* row = src + (size_t)s * DIM;
    __half* orow = dst + (size_t)s * DIM;
    __shared__ float red[256];

    float ss = 0.f;
    for (int i = threadIdx.x; i < DIM; i += 256) {
        float v = row[i];
        ss += v * v;
    }
    red[threadIdx.x] = ss;
    __syncthreads();
    for (int off = 128; off > 0; off >>= 1) {
        if (threadIdx.x < off) red[threadIdx.x] += red[threadIdx.x + off];
        __syncthreads();
    }
    const float scale = rsqrtf(red[0] * (1.0f / DIM) + 1e-6f);

    const int hh = s / W_GRID;
    const int ww = s % W_GRID;
    for (int p = threadIdx.x; p < NH * 64; p += 256) {
        const int head = p >> 6;
        const int c = p & 63;
        const int trow = (c < 22) ? 6 : ((c < 43) ? hh : ww);
        const float cv = fcos[trow * 64 + c];
        const float sv = fsin[trow * 64 + c];
        const int base = head * HD + 2 * c;
        const float xr = row[base] * scale * g[base];
        const float xi = row[base + 1] * scale * g[base + 1];
        *(unsigned*)(orow + base) =
            pack_h2((xr * cv - xi * sv) * oscale, (xr * sv + xi * cv) * oscale);
    }
}

// ---------------------------------------------------------------------------
// fp16 flash attention, m16n8k16 + ldmatrix. BQ=144 x BK=64, 9 warps.
// Round 8: Q fragments hoisted to registers (loaded once), K AND V double-
// buffered -> exactly ONE __syncthreads per tile; P stays warp-private.
// ---------------------------------------------------------------------------
#define BQ 144
#define BK 64
#define QSH 136
#define KSH 136
#define VSH 136
#define PSH 72
#define NTHR 288

struct __align__(16) AttnSmem {
    __half Qs[BQ * QSH];        // 39168 B
    __half Ks[2][BK * KSH];     // 2 x 17408 B
    __half Vs[2][BK * VSH];     // 2 x 17408 B
    __half Ps[BQ * PSH];        // 20736 B
};
#define ATTN_SMEM ((int)sizeof(AttnSmem))   // 129536 B

__global__ __launch_bounds__(NTHR, 1)
void attn_tc_kernel(const __half* __restrict__ qh, float* __restrict__ out) {
    extern __shared__ char smraw[];
    AttnSmem* sm = (AttnSmem*)smraw;

    const int head = blockIdx.y;
    const int q0 = blockIdx.x * BQ;
    const int tid = threadIdx.x;
    const int lane = tid & 31;
    const int w = tid >> 5;          // 0..8
    const int g = lane >> 2;
    const int tg = lane & 3;
    const int wq = w * 16;
    const int r0 = wq + g;
    const int r1 = wq + g + 8;

    const unsigned smem_base = (unsigned)__cvta_generic_to_shared(sm);
    const unsigned qs_b  = smem_base;
    const unsigned ks_b[2] = {
        smem_base + (unsigned)((char*)sm->Ks[0] - (char*)sm),
        smem_base + (unsigned)((char*)sm->Ks[1] - (char*)sm) };
    const unsigned vs_b[2] = {
        smem_base + (unsigned)((char*)sm->Vs[0] - (char*)sm),
        smem_base + (unsigned)((char*)sm->Vs[1] - (char*)sm) };
    const unsigned ps_b  = smem_base + (unsigned)((char*)sm->Ps - (char*)sm);

    // ldmatrix per-lane address components (byte offsets)
    const unsigned qa_off = qs_b + (((wq + (lane & 15)) * QSH + (lane >> 4) * 8) * 2);
    const unsigned kb_off = ((((lane >> 4) & 1) * 8 + (lane & 7)) * KSH +
                             ((lane >> 3) & 1) * 8) * 2;
    const unsigned pa_off = ps_b + (((wq + (lane & 15)) * PSH + (lane >> 4) * 8) * 2);
    const unsigned vb_off = (((((lane >> 3) & 1) * 8 + (lane & 7)) * VSH +
                              ((lane >> 4) & 1) * 8) * 2);

    // loaders (threads 0..255): K/V tiles, 4 x 16B each per tile
    const bool loader = tid < 256;
    const int lr = tid >> 2;            // 0..63
    const int lc = (tid & 3) * 32;      // half col base (64B)

    // ---- load Q tile into smem (fp16, pre-scaled), zero-pad tail rows ----
    {
        const int r = tid >> 1;          // 0..143
        const int cb = (tid & 1) * 64;
        const int srow = q0 + r;
        const bool valid = srow < S_TOK;
        const __half* src = qh + (size_t)srow * DIM + head * HD + cb;
        const uint4 z = make_uint4(0, 0, 0, 0);
#pragma unroll
        for (int m2 = 0; m2 < 8; m2++) {
            uint4 v = valid ? *(const uint4*)(src + m2 * 8) : z;
            *(uint4*)&sm->Qs[r * QSH + cb + m2 * 8] = v;
        }
    }

    const int NT = (L_TOT + BK - 1) / BK;  // 171

    // prologue: issue K(0) + V(0) into buffer 0
    if (loader) {
        const int kidx = min(lr, L_TOT - 1);
        const __half* ksrc = g_ckh + (size_t)kidx * DIM + head * HD + lc;
        const __half* vsrc = g_cvh + (size_t)kidx * DIM + head * HD + lc;
#pragma unroll
        for (int i = 0; i < 4; i++)
            cp16(ks_b[0] + (lr * KSH + lc + i * 8) * 2, ksrc + i * 8);
#pragma unroll
        for (int i = 0; i < 4; i++)
            cp16(vs_b[0] + (lr * VSH + lc + i * 8) * 2, vsrc + i * 8);
    }
    cp_commit();

    __syncthreads();   // Q smem complete

    // ---- hoist Q fragments into registers (loop-invariant) ----
    unsigned qa[8][4];
#pragma unroll
    for (int kf = 0; kf < 8; kf++)
        ldsm4(qa[kf][0], qa[kf][1], qa[kf][2], qa[kf][3], qa_off + kf * 32);

    float acc[16][4];
#pragma unroll
    for (int nf = 0; nf < 16; nf++)
#pragma unroll
        for (int j = 0; j < 4; j++) acc[nf][j] = 0.f;

    float m0 = -1e30f, m1 = -1e30f, l0 = 0.f, l1 = 0.f;

    for (int t = 0; t < NT; t++) {
        const int kbase = t * BK;
        const int buf = t & 1;

        cp_wait<0>();      // K(t)/V(t) landed
        __syncthreads();   // visible to all warps; prev-tile reads finished

        // issue K(t+1) + V(t+1) into the other buffer
        if (loader && t + 1 < NT) {
            const int kidx = min((t + 1) * BK + lr, L_TOT - 1);
            const __half* ksrc = g_ckh + (size_t)kidx * DIM + head * HD + lc;
            const __half* vsrc = g_cvh + (size_t)kidx * DIM + head * HD + lc;
            const unsigned kb = ks_b[buf ^ 1];
            const unsigned vb = vs_b[buf ^ 1];
#pragma unroll
            for (int i = 0; i < 4; i++)
                cp16(kb + (lr * KSH + lc + i * 8) * 2, ksrc + i * 8);
#pragma unroll
            for (int i = 0; i < 4; i++)
                cp16(vb + (lr * VSH + lc + i * 8) * 2, vsrc + i * 8);
        }
        cp_commit();

        // ---- scores: warp = 16q x 64k, 8 kf x 8 nf mmas ----
        float sc[8][4];
#pragma unroll
        for (int nf = 0; nf < 8; nf++)
#pragma unroll
            for (int j = 0; j < 4; j++) sc[nf][j] = 0.f;

        const unsigned ksb = ks_b[buf];
#pragma unroll
        for (int kf = 0; kf < 8; kf++) {
#pragma unroll
            for (int nfp = 0; nfp < 4; nfp++) {
                unsigned b00, b01, b10, b11;
                ldsm4(b00, b01, b10, b11, ksb + nfp * (16 * KSH * 2) + kb_off + kf * 32);
                mma_f16(sc[2 * nfp],     qa[kf][0], qa[kf][1], qa[kf][2], qa[kf][3], b00, b01);
                mma_f16(sc[2 * nfp + 1], qa[kf][0], qa[kf][1], qa[kf][2], qa[kf][3], b10, b11);
            }
        }

        // ---- mask tail tile ----
        if (kbase + BK > L_TOT) {
#pragma unroll
            for (int nf = 0; nf < 8; nf++) {
                const int c0 = kbase + nf * 8 + 2 * tg;
                if (c0 >= L_TOT)     { sc[nf][0] = -1e30f; sc[nf][2] = -1e30f; }
                if (c0 + 1 >= L_TOT) { sc[nf][1] = -1e30f; sc[nf][3] = -1e30f; }
            }
        }

        // ---- in-register softmax (rows r0, r1), base-2 domain ----
        float mx0 = -1e30f, mx1 = -1e30f;
#pragma unroll
        for (int nf = 0; nf < 8; nf++) {
            mx0 = fmaxf(mx0, fmaxf(sc[nf][0], sc[nf][1]));
            mx1 = fmaxf(mx1, fmaxf(sc[nf][2], sc[nf][3]));
        }
        mx0 = fmaxf(mx0, __shfl_xor_sync(0xffffffffu, mx0, 1));
        mx0 = fmaxf(mx0, __shfl_xor_sync(0xffffffffu, mx0, 2));
        mx1 = fmaxf(mx1, __shfl_xor_sync(0xffffffffu, mx1, 1));
        mx1 = fmaxf(mx1, __shfl_xor_sync(0xffffffffu, mx1, 2));
        const float mn0 = fmaxf(m0, mx0);
        const float mn1 = fmaxf(m1, mx1);
        const float al0 = exp2f(m0 - mn0);
        const float al1 = exp2f(m1 - mn1);

        float s0 = 0.f, s1 = 0.f;
#pragma unroll
        for (int nf = 0; nf < 8; nf++) {
            const float p00 = exp2f(sc[nf][0] - mn0);
            const float p01 = exp2f(sc[nf][1] - mn0);
            const float p10 = exp2f(sc[nf][2] - mn1);
            const float p11 = exp2f(sc[nf][3] - mn1);
            s0 += p00 + p01;
            s1 += p10 + p11;
            const int col = nf * 8 + 2 * tg;
            *(unsigned*)&sm->Ps[r0 * PSH + col] = pack_h2(p00, p01);
            *(unsigned*)&sm->Ps[r1 * PSH + col] = pack_h2(p10, p11);
        }
        s0 += __shfl_xor_sync(0xffffffffu, s0, 1);
        s0 += __shfl_xor_sync(0xffffffffu, s0, 2);
        s1 += __shfl_xor_sync(0xffffffffu, s1, 1);
        s1 += __shfl_xor_sync(0xffffffffu, s1, 2);
        l0 = l0 * al0 + s0;
        l1 = l1 * al1 + s1;
        m0 = mn0;
        m1 = mn1;

        __syncwarp();      // own-row P visible to this warp's ldmatrix

        // rescale accumulators
#pragma unroll
        for (int nf = 0; nf < 16; nf++) {
            acc[nf][0] *= al0; acc[nf][1] *= al0;
            acc[nf][2] *= al1; acc[nf][3] *= al1;
        }

        // ---- PV: warp = 16q x 128hd over 64 k, 4 kf x 16 nf mmas ----
        const unsigned vsb = vs_b[buf];
#pragma unroll
        for (int kf = 0; kf < 4; kf++) {
            unsigned a0, a1, a2, a3;
            ldsm4(a0, a1, a2, a3, pa_off + kf * 32);
#pragma unroll
            for (int nfp = 0; nfp < 8; nfp++) {
                unsigned b00, b01, b10, b11;
                ldsm4t(b00, b01, b10, b11,
                       vsb + vb_off + kf * (16 * VSH * 2) + nfp * 32);
                mma_f16(acc[2 * nfp],     a0, a1, a2, a3, b00, b01);
                mma_f16(acc[2 * nfp + 1], a0, a1, a2, a3, b10, b11);
            }
        }
        // no trailing barrier: next tile's top barrier provides the ordering
    }

    // ---- epilogue ----
    {
        const float inv0 = 1.0f / l0;
        const float inv1 = 1.0f / l1;
        const int row0 = q0 + r0;
        const int row1 = q0 + r1;
#pragma unroll
        for (int nf = 0; nf < 16; nf++) {
            const int col = head * HD + nf * 8 + 2 * tg;
            if (row0 < S_TOK)
                *(float2*)(out + (size_t)row0 * DIM + col) =
                    make_float2(acc[nf][0] * inv0, acc[nf][1] * inv0);
            if (row1 < S_TOK)
                *(float2*)(out + (size_t)row1 * DIM + col) =
                    make_float2(acc[nf][2] * inv1, acc[nf][3] * inv1);
        }
    }
}

// ---------------------------------------------------------------------------
extern "C" void kernel_launch(void* const* d_in, const int* in_sizes, int n_in,
                              void* d_out, int out_size) {
    (void)in_sizes; (void)n_in; (void)out_size;
    const float* x    = (const float*)d_in[0];
    const float* wq   = (const float*)d_in[1];
    const float* bq   = (const float*)d_in[2];
    const float* wk   = (const float*)d_in[3];
    const float* bk   = (const float*)d_in[4];
    const float* wv   = (const float*)d_in[5];
    const float* bv   = (const float*)d_in[6];
    const float* wo   = (const float*)d_in[7];
    const float* bo   = (const float*)d_in[8];
    const float* gq   = (const float*)d_in[9];
    const float* gk   = (const float*)d_in[10];
    const float* fcos = (const float*)d_in[11];
    const float* fsin = (const float*)d_in[12];
    const float* ck   = (const float*)d_in[13];
    const float* cvv  = (const float*)d_in[14];

    float *q, *k, *o;
    __half *qh, *ckh;
    cudaGetSymbolAddress((void**)&q, g_q);
    cudaGetSymbolAddress((void**)&k, g_k);
    cudaGetSymbolAddress((void**)&o, g_o);
    cudaGetSymbolAddress((void**)&qh, g_qh);
    cudaGetSymbolAddress((void**)&ckh, g_ckh);

    cudaFuncSetAttribute(attn_tc_kernel, cudaFuncAttributeMaxDynamicSharedMemorySize,
                         ATTN_SMEM);

    // 1. preround cache K/V into fp16 scratch
    preround_kernel<<<1024, 256>>>(ck, cvv);

    // 2. fused Q/K/V projections (V written fp16 into g_cvh tail)
    dim3 qkvgrid(DIM / 128, (S_TOK + 127) / 128, 3);  // (12, 13, 3)
    gemm_qkv_kernel<<<qkvgrid, 256>>>(x, wq, bq, wk, bk, wv, bv, S_TOK);

    // 3. norm + rope: Q scaled to base-2 score domain -> g_qh; K -> g_ckh tail
    norm_rope_kernel<<<S_TOK, 256>>>(q, qh, gq, fcos, fsin, SCALE_LOG2E);
    norm_rope_kernel<<<S_TOK, 256>>>(k, ckh + (size_t)CUR * DIM, gk, fcos, fsin, 1.0f);

    // 4. attention (132 blocks, single wave)
    dim3 agrid((S_TOK + BQ - 1) / BQ, NH);  // (11, 12)
    attn_tc_kernel<<<agrid, NTHR, ATTN_SMEM>>>(qh, o);

    // 5. output projection
    dim3 ogrid(DIM / 128, (S_TOK + 127) / 128);  // (12, 13)
    gemm_out_kernel<<<ogrid, 256>>>(o, wo, bo, (float*)d_out, S_TOK);
}